// round 4
// baseline (speedup 1.0000x reference)
#include <cuda_runtime.h>
#include <cuda_bf16.h>
#include <math.h>

// Problem constants
#define Bq 256      // sentences (batch for LSTMs, sequence for CRF)
#define Tt 128      // words per sentence
#define Ff 768      // feature size
#define HH 256      // word LSTM hidden
#define G4 1024     // 4*HH
#define H2 512      // 2*HH (sentence LSTM hidden)
#define G8 2048     // 4*H2
#define NC 16       // num classes

#define GXR_OFF 33554432   // 256*128*1024

typedef unsigned long long ull;

// ---------------- packed f32x2 helpers (Blackwell FFMA2) ---------------------
__device__ __forceinline__ ull pk2(float lo, float hi) {
    ull r; asm("mov.b64 %0,{%1,%2};" : "=l"(r) : "f"(lo), "f"(hi)); return r;
}
__device__ __forceinline__ void fma2(ull& d, ull a, ull b) {
    asm("fma.rn.f32x2 %0,%1,%2,%0;" : "+l"(d) : "l"(a), "l"(b));
}
__device__ __forceinline__ float2 up2(ull v) {
    float2 r; asm("mov.b64 {%0,%1},%2;" : "=f"(r.x), "=f"(r.y) : "l"(v)); return r;
}

// ---------------- tf32 helpers ------------------------------------------------
__device__ __forceinline__ unsigned cvt_tf32(float v) {
    unsigned r; asm("cvt.rna.tf32.f32 %0, %1;" : "=r"(r) : "f"(v)); return r;
}
__device__ __forceinline__ void mma_tf32(float c[4], const unsigned a[4], const unsigned b[2]) {
    asm("mma.sync.aligned.m16n8k8.row.col.f32.tf32.tf32.f32 "
        "{%0,%1,%2,%3}, {%4,%5,%6,%7}, {%8,%9}, {%0,%1,%2,%3};"
        : "+f"(c[0]), "+f"(c[1]), "+f"(c[2]), "+f"(c[3])
        : "r"(a[0]), "r"(a[1]), "r"(a[2]), "r"(a[3]), "r"(b[0]), "r"(b[1]));
}

// ---------------- scratch (static device memory; no allocations) ------------
__device__ float g_big[67108864];          // gx_f | gx_r, later reused as gx_s (256MB)
__device__ float g_hcat[Bq * Tt * H2];     // [B][T][512] word BiLSTM outputs (64MB)
__device__ float g_wpf[HH * G4];           // packed w_hh_f: [k][n][4 gates]
__device__ float g_wpr[HH * G4];
__device__ float g_wps[H2 * G8];
__device__ float g_hw[2][2][Bq][HH];       // word h state [dir][buf][b][n]
__device__ float g_hs[2][Bq][H2];          // sentence h state [buf][b][n]

__device__ unsigned g_bar_cnt = 0;
__device__ unsigned g_bar_gen = 0;

// software grid barrier: all CTAs guaranteed co-resident (grid <= 148, 1 CTA/SM)
__device__ __forceinline__ void grid_barrier(unsigned ncta) {
    __syncthreads();
    if (threadIdx.x == 0) {
        volatile unsigned* genp = &g_bar_gen;
        unsigned gen = *genp;
        __threadfence();
        if (atomicAdd(&g_bar_cnt, 1u) == ncta - 1u) {
            atomicExch(&g_bar_cnt, 0u);
            __threadfence();
            atomicExch(&g_bar_gen, gen + 1u);
        } else {
            while (*genp == gen) { }
        }
        __threadfence();
    }
    __syncthreads();
}

// ---------------- pack recurrent weights: in [4H][H] -> out [(k*H+n)*4+g] ----
__global__ void pack_whh(const float* __restrict__ in, float* __restrict__ out, int H) {
    int idx = blockIdx.x * blockDim.x + threadIdx.x;
    if (idx < 4 * H * H) {
        int g = idx & 3;
        int rem = idx >> 2;
        int n = rem % H;
        int k = rem / H;
        out[idx] = in[(size_t)(g * H + n) * H + k];
    }
}

// ---------------- TF32 tensor-core GEMM --------------------------------------
// C[m][n] = sum_k A[m][k]*W[n][k] + bias[n].  A:[M,K] rm, W:[N,K] rm.
// CTA 128x128, BK=16, 8 warps as 2(m) x 4(n), warp tile 64x32.
#define BKK 16
#define SPAD 8
#define SST (128 + SPAD)   // smem row stride (uint32 elems); 136 % 32 == 8 -> conflict-free frags
__global__ void __launch_bounds__(256) gemm_tf32(
    const float* __restrict__ A, const float* __restrict__ W,
    const float* __restrict__ bias, float* __restrict__ C,
    int M, int N, int K)
{
    __shared__ unsigned As[BKK][SST];
    __shared__ unsigned Bs[BKK][SST];
    int tid = threadIdx.x;
    int lane = tid & 31, wid = tid >> 5;
    int wm = wid >> 2;        // 0..1   (64 rows each)
    int wn = wid & 3;         // 0..3   (32 cols each)
    int lq = lane >> 2;       // 0..7
    int lr4 = lane & 3;       // 0..3

    const float* Ab = A + (size_t)blockIdx.y * 128 * K;
    const float* Wb = W + (size_t)blockIdx.x * 128 * K;
    int ldr = tid >> 1;             // 0..127 (row within tile)
    int ldk = (tid & 1) * 8;        // 0 or 8

    float acc[4][4][4];
#pragma unroll
    for (int i = 0; i < 4; i++)
#pragma unroll
        for (int j = 0; j < 4; j++)
#pragma unroll
            for (int r = 0; r < 4; r++) acc[i][j][r] = 0.f;

    for (int k0 = 0; k0 < K; k0 += BKK) {
        // load A,W tiles -> smem (k-major, tf32-converted)
        float4 a0 = *(const float4*)(Ab + (size_t)ldr * K + k0 + ldk);
        float4 a1 = *(const float4*)(Ab + (size_t)ldr * K + k0 + ldk + 4);
        float4 w0 = *(const float4*)(Wb + (size_t)ldr * K + k0 + ldk);
        float4 w1 = *(const float4*)(Wb + (size_t)ldr * K + k0 + ldk + 4);
        As[ldk + 0][ldr] = cvt_tf32(a0.x); As[ldk + 1][ldr] = cvt_tf32(a0.y);
        As[ldk + 2][ldr] = cvt_tf32(a0.z); As[ldk + 3][ldr] = cvt_tf32(a0.w);
        As[ldk + 4][ldr] = cvt_tf32(a1.x); As[ldk + 5][ldr] = cvt_tf32(a1.y);
        As[ldk + 6][ldr] = cvt_tf32(a1.z); As[ldk + 7][ldr] = cvt_tf32(a1.w);
        Bs[ldk + 0][ldr] = cvt_tf32(w0.x); Bs[ldk + 1][ldr] = cvt_tf32(w0.y);
        Bs[ldk + 2][ldr] = cvt_tf32(w0.z); Bs[ldk + 3][ldr] = cvt_tf32(w0.w);
        Bs[ldk + 4][ldr] = cvt_tf32(w1.x); Bs[ldk + 5][ldr] = cvt_tf32(w1.y);
        Bs[ldk + 6][ldr] = cvt_tf32(w1.z); Bs[ldk + 7][ldr] = cvt_tf32(w1.w);
        __syncthreads();

#pragma unroll
        for (int ks = 0; ks < 2; ks++) {
            int kb = ks * 8;
            unsigned af[4][4];
#pragma unroll
            for (int mf = 0; mf < 4; mf++) {
                int row = wm * 64 + mf * 16 + lq;
                af[mf][0] = As[kb + lr4][row];
                af[mf][1] = As[kb + lr4][row + 8];
                af[mf][2] = As[kb + lr4 + 4][row];
                af[mf][3] = As[kb + lr4 + 4][row + 8];
            }
            unsigned bf[4][2];
#pragma unroll
            for (int nf = 0; nf < 4; nf++) {
                int n = wn * 32 + nf * 8 + lq;
                bf[nf][0] = Bs[kb + lr4][n];
                bf[nf][1] = Bs[kb + lr4 + 4][n];
            }
#pragma unroll
            for (int mf = 0; mf < 4; mf++)
#pragma unroll
                for (int nf = 0; nf < 4; nf++)
                    mma_tf32(acc[mf][nf], af[mf], bf[nf]);
        }
        __syncthreads();
    }

    // epilogue: add bias, store
#pragma unroll
    for (int nf = 0; nf < 4; nf++) {
        int col0 = blockIdx.x * 128 + wn * 32 + nf * 8 + 2 * lr4;
        float b0v = bias[col0], b1v = bias[col0 + 1];
#pragma unroll
        for (int mf = 0; mf < 4; mf++) {
            int row0 = blockIdx.y * 128 + wm * 64 + mf * 16 + lq;
            float2 o0 = make_float2(acc[mf][nf][0] + b0v, acc[mf][nf][1] + b1v);
            float2 o1 = make_float2(acc[mf][nf][2] + b0v, acc[mf][nf][3] + b1v);
            *(float2*)(C + (size_t)row0 * N + col0) = o0;
            *(float2*)(C + (size_t)(row0 + 8) * N + col0) = o1;
        }
    }
}

__device__ __forceinline__ float sigmoidf(float x) { return 1.f / (1.f + expf(-x)); }

// ---------------- word BiLSTM persistent scan --------------------------------
// 128 CTAs: 64 per direction. CTA tile = 32 b x 32 n x 4 gates.
__global__ void __launch_bounds__(256) word_scan_kernel() {
    extern __shared__ __align__(16) float2 h_d[];   // [32][HH] dup pairs = 64KB
    int cta = blockIdx.x;
    int dir = cta & 1;
    int id = cta >> 1;                // 0..63
    int bt = id >> 3;                 // 0..7 (32 b each)
    int nt = id & 7;                  // 0..7 (32 n each)
    const float* gxp = dir ? (g_big + GXR_OFF) : g_big;
    const float* wp  = dir ? g_wpr : g_wpf;

    int lane = threadIdx.x & 31;
    int wg   = threadIdx.x >> 5;
    int n = nt * 32 + lane;
    int b0 = bt * 32 + wg * 4;
    const float* wbase = wp + (size_t)n * 4;   // + k*HH*4 per k

    float c_reg[4] = {0.f, 0.f, 0.f, 0.f};

#pragma unroll
    for (int u = 0; u < 4; u++) g_hw[dir][0][b0 + u][n] = 0.f;
    grid_barrier(128);

    for (int t = 0; t < Tt; t++) {
        int tt = dir ? (Tt - 1 - t) : t;
        int rb = t & 1, wb = rb ^ 1;
        const float4* hsrc = (const float4*)&g_hw[dir][rb][bt * 32][0];
        float4* hdst = (float4*)h_d;
        for (int idx = threadIdx.x; idx < 32 * HH / 4; idx += 256) {
            float4 v = hsrc[idx];
            hdst[idx * 2]     = make_float4(v.x, v.x, v.y, v.y);
            hdst[idx * 2 + 1] = make_float4(v.z, v.z, v.w, v.w);
        }
        __syncthreads();

        ull acc01[4], acc23[4];
#pragma unroll
        for (int u = 0; u < 4; u++) {
            const float* gp = gxp + ((size_t)(b0 + u) * Tt + tt) * G4 + n;
            acc01[u] = pk2(gp[0], gp[HH]);
            acc23[u] = pk2(gp[2 * HH], gp[3 * HH]);
        }
        const ull* hrow0 = (const ull*)h_d + (size_t)(wg * 4) * HH;
#pragma unroll 8
        for (int k = 0; k < HH; k++) {
            ulonglong2 wv = *(const ulonglong2*)(wbase + (size_t)k * (HH * 4));
            ull h0 = hrow0[k];
            ull h1 = hrow0[HH + k];
            ull h2 = hrow0[2 * HH + k];
            ull h3 = hrow0[3 * HH + k];
            fma2(acc01[0], h0, wv.x); fma2(acc23[0], h0, wv.y);
            fma2(acc01[1], h1, wv.x); fma2(acc23[1], h1, wv.y);
            fma2(acc01[2], h2, wv.x); fma2(acc23[2], h2, wv.y);
            fma2(acc01[3], h3, wv.x); fma2(acc23[3], h3, wv.y);
        }
#pragma unroll
        for (int u = 0; u < 4; u++) {
            float2 p01 = up2(acc01[u]);
            float2 p23 = up2(acc23[u]);
            float ig = sigmoidf(p01.x);
            float fg = sigmoidf(p01.y);
            float gg = tanhf(p23.x);
            float og = sigmoidf(p23.y);
            c_reg[u] = fg * c_reg[u] + ig * gg;
            float h = og * tanhf(c_reg[u]);
            g_hw[dir][wb][b0 + u][n] = h;
            g_hcat[((size_t)(b0 + u) * Tt + tt) * H2 + dir * HH + n] = h;
        }
        grid_barrier(128);
    }
}

// ---------------- sentence LSTM persistent scan -------------------------------
__global__ void __launch_bounds__(256) sent_scan_kernel() {
    extern __shared__ __align__(16) float2 h_d[];   // [32][H2] dup pairs = 128KB
    int cta = blockIdx.x;
    int bt = cta >> 4;                // 0..7
    int nt = cta & 15;                // 0..15
    int lane = threadIdx.x & 31;
    int wg   = threadIdx.x >> 5;
    int n = nt * 32 + lane;
    int b0 = bt * 32 + wg * 4;
    const float* gxs = g_big;
    const float* wbase = g_wps + (size_t)n * 4;
    float c_reg[4] = {0.f, 0.f, 0.f, 0.f};

#pragma unroll
    for (int u = 0; u < 4; u++) g_hs[0][b0 + u][n] = 0.f;
    grid_barrier(128);

    for (int t = 0; t < Tt; t++) {
        int rb = t & 1, wb = rb ^ 1;
        const float4* hsrc = (const float4*)&g_hs[rb][bt * 32][0];
        float4* hdst = (float4*)h_d;
        for (int idx = threadIdx.x; idx < 32 * H2 / 4; idx += 256) {
            float4 v = hsrc[idx];
            hdst[idx * 2]     = make_float4(v.x, v.x, v.y, v.y);
            hdst[idx * 2 + 1] = make_float4(v.z, v.z, v.w, v.w);
        }
        __syncthreads();

        ull acc01[4], acc23[4];
#pragma unroll
        for (int u = 0; u < 4; u++) {
            const float* gp = gxs + ((size_t)(b0 + u) * Tt + t) * G8 + n;
            acc01[u] = pk2(gp[0], gp[H2]);
            acc23[u] = pk2(gp[2 * H2], gp[3 * H2]);
        }
        const ull* hrow0 = (const ull*)h_d + (size_t)(wg * 4) * H2;
#pragma unroll 8
        for (int k = 0; k < H2; k++) {
            ulonglong2 wv = *(const ulonglong2*)(wbase + (size_t)k * (H2 * 4));
            ull h0 = hrow0[k];
            ull h1 = hrow0[H2 + k];
            ull h2 = hrow0[2 * H2 + k];
            ull h3 = hrow0[3 * H2 + k];
            fma2(acc01[0], h0, wv.x); fma2(acc23[0], h0, wv.y);
            fma2(acc01[1], h1, wv.x); fma2(acc23[1], h1, wv.y);
            fma2(acc01[2], h2, wv.x); fma2(acc23[2], h2, wv.y);
            fma2(acc01[3], h3, wv.x); fma2(acc23[3], h3, wv.y);
        }
#pragma unroll
        for (int u = 0; u < 4; u++) {
            float2 p01 = up2(acc01[u]);
            float2 p23 = up2(acc23[u]);
            float ig = sigmoidf(p01.x);
            float fg = sigmoidf(p01.y);
            float gg = tanhf(p23.x);
            float og = sigmoidf(p23.y);
            c_reg[u] = fg * c_reg[u] + ig * gg;
            float h = og * tanhf(c_reg[u]);
            g_hs[wb][b0 + u][n] = h;   // t=127 writes buf 0 -> hT
        }
        grid_barrier(128);
    }
}

// ---------------- emissions + CRF (single block) ------------------------------
__global__ void __launch_bounds__(256) crf_kernel(
    const int* __restrict__ y,
    const float* __restrict__ lin_w, const float* __restrict__ lin_b,
    const float* __restrict__ cstart, const float* __restrict__ cend,
    const float* __restrict__ ctrans, float* __restrict__ out)
{
    __shared__ float pool[NC * H2];   // 32KB: lin_w staging, later tr/alpha
    __shared__ float e[Bq][NC];       // 16KB
    int tid = threadIdx.x;

    for (int idx = tid; idx < NC * H2 / 4; idx += 256)
        ((float4*)pool)[idx] = ((const float4*)lin_w)[idx];
    __syncthreads();

    {
        const float* hrow = &g_hs[0][tid][0];
        float acc[NC];
#pragma unroll
        for (int c = 0; c < NC; c++) acc[c] = lin_b[c];
        for (int k = 0; k < H2; k += 4) {
            float4 hv = *(const float4*)(hrow + k);
#pragma unroll
            for (int c = 0; c < NC; c++) {
                const float* wr = pool + c * H2 + k;
                acc[c] += hv.x * wr[0] + hv.y * wr[1] + hv.z * wr[2] + hv.w * wr[3];
            }
        }
#pragma unroll
        for (int c = 0; c < NC; c++) e[tid][c] = acc[c];
    }
    __syncthreads();

    if (tid < NC * NC) pool[tid] = ctrans[tid];
    __syncthreads();
    float* tr = pool;
    float* alpha = pool + 256;
    float* alpha2 = pool + 288;

    if (tid < NC) alpha[tid] = cstart[tid] + e[0][tid];
    __syncthreads();

    if (tid < 32) {
        for (int s = 1; s < Bq; s++) {
            if (tid < NC) {
                int j = tid;
                float m = -1e30f;
#pragma unroll
                for (int i = 0; i < NC; i++) m = fmaxf(m, alpha[i] + tr[i * NC + j]);
                float sum = 0.f;
#pragma unroll
                for (int i = 0; i < NC; i++) sum += expf(alpha[i] + tr[i * NC + j] - m);
                alpha2[j] = m + logf(sum) + e[s][j];
            }
            __syncwarp();
            if (tid < NC) alpha[tid] = alpha2[tid];
            __syncwarp();
        }
    }
    __syncthreads();

    if (tid == 0) {
        int yprev = y[0];
        float num = cstart[yprev] + e[0][yprev];
        for (int s = 1; s < Bq; s++) {
            int ys = y[s];
            num += tr[yprev * NC + ys] + e[s][ys];
            yprev = ys;
        }
        num += cend[yprev];

        float m = -1e30f;
        for (int i = 0; i < NC; i++) m = fmaxf(m, alpha[i] + cend[i]);
        float sum = 0.f;
        for (int i = 0; i < NC; i++) sum += expf(alpha[i] + cend[i] - m);
        float denom = m + logf(sum);
        out[0] = num - denom;
    }
}

// ---------------- launch ------------------------------------------------------
extern "C" void kernel_launch(void* const* d_in, const int* in_sizes, int n_in,
                              void* d_out, int out_size)
{
    const float* x      = (const float*)d_in[0];
    const int*   y      = (const int*)  d_in[1];
    // d_in[2] = mask (unused by the reference math)
    const float* w_ih_f = (const float*)d_in[3];
    const float* w_hh_f = (const float*)d_in[4];
    const float* b_f    = (const float*)d_in[5];
    const float* w_ih_r = (const float*)d_in[6];
    const float* w_hh_r = (const float*)d_in[7];
    const float* b_r    = (const float*)d_in[8];
    const float* w_ih_s = (const float*)d_in[9];
    const float* w_hh_s = (const float*)d_in[10];
    const float* b_s    = (const float*)d_in[11];
    const float* lin_w  = (const float*)d_in[12];
    const float* lin_b  = (const float*)d_in[13];
    const float* cstart = (const float*)d_in[14];
    const float* cend   = (const float*)d_in[15];
    const float* ctrans = (const float*)d_in[16];
    float* out = (float*)d_out;

    float *gbig, *hcat, *wpf, *wpr, *wps;
    cudaGetSymbolAddress((void**)&gbig, g_big);
    cudaGetSymbolAddress((void**)&hcat, g_hcat);
    cudaGetSymbolAddress((void**)&wpf, g_wpf);
    cudaGetSymbolAddress((void**)&wpr, g_wpr);
    cudaGetSymbolAddress((void**)&wps, g_wps);

    cudaFuncSetAttribute(word_scan_kernel,
                         cudaFuncAttributeMaxDynamicSharedMemorySize, 65536);
    cudaFuncSetAttribute(sent_scan_kernel,
                         cudaFuncAttributeMaxDynamicSharedMemorySize, 131072);

    // pack recurrent weights into [k][n][4-gate] layout (f32x2-friendly)
    pack_whh<<<(4 * HH * HH + 255) / 256, 256>>>(w_hh_f, wpf, HH);
    pack_whh<<<(4 * HH * HH + 255) / 256, 256>>>(w_hh_r, wpr, HH);
    pack_whh<<<(4 * H2 * H2 + 255) / 256, 256>>>(w_hh_s, wps, H2);

    // input projections (bias fused) -- TF32 tensor cores
    dim3 g1(G4 / 128, (Bq * Tt) / 128);
    gemm_tf32<<<g1, 256>>>(x, w_ih_f, b_f, gbig, Bq * Tt, G4, Ff);
    gemm_tf32<<<g1, 256>>>(x, w_ih_r, b_r, gbig + GXR_OFF, Bq * Tt, G4, Ff);

    // word BiLSTM scan -> g_hcat
    word_scan_kernel<<<128, 256, 65536>>>();

    // sentence input projection (reuses g_big as gx_s)
    dim3 g2(G8 / 128, (Bq * Tt) / 128);
    gemm_tf32<<<g2, 256>>>(hcat, w_ih_s, b_s, gbig, Bq * Tt, G8, H2);

    // sentence LSTM scan -> g_hs[0] = hT
    sent_scan_kernel<<<128, 256, 131072>>>();

    // emissions + CRF -> scalar
    crf_kernel<<<1, 256>>>(y, lin_w, lin_b, cstart, cend, ctrans, out);
}

// round 5
// speedup vs baseline: 2.0487x; 2.0487x over previous
#include <cuda_runtime.h>
#include <math.h>

#define Bq 256
#define Tt 128
#define Ff 768
#define HH 256
#define G4 1024
#define H2 512
#define G8 2048
#define NC 16
#define GXR_OFF 33554432

typedef unsigned long long ull;

__device__ __forceinline__ ull pk2(float lo, float hi) {
    ull r; asm("mov.b64 %0,{%1,%2};" : "=l"(r) : "f"(lo), "f"(hi)); return r;
}
__device__ __forceinline__ void fma2(ull& d, ull a, ull b) {
    asm("fma.rn.f32x2 %0,%1,%2,%0;" : "+l"(d) : "l"(a), "l"(b));
}
__device__ __forceinline__ float2 up2(ull v) {
    float2 r; asm("mov.b64 {%0,%1},%2;" : "=f"(r.x), "=f"(r.y) : "l"(v)); return r;
}
__device__ __forceinline__ unsigned cvt_tf32(float v) {
    unsigned r; asm("cvt.rna.tf32.f32 %0, %1;" : "=r"(r) : "f"(v)); return r;
}
__device__ __forceinline__ void mma_tf32(float c[4], const unsigned a[4], const unsigned b[2]) {
    asm("mma.sync.aligned.m16n8k8.row.col.f32.tf32.tf32.f32 "
        "{%0,%1,%2,%3}, {%4,%5,%6,%7}, {%8,%9}, {%0,%1,%2,%3};"
        : "+f"(c[0]), "+f"(c[1]), "+f"(c[2]), "+f"(c[3])
        : "r"(a[0]), "r"(a[1]), "r"(a[2]), "r"(a[3]), "r"(b[0]), "r"(b[1]));
}

__device__ float g_big[67108864];
__device__ float g_hcat[Bq * Tt * H2];
__device__ float g_wpf[HH * G4];
__device__ float g_wpr[HH * G4];
__device__ float g_wps[H2 * G8];
__device__ float g_hw[2][2][Bq][HH];
__device__ float g_hs[2][Bq][H2];

__device__ unsigned g_cnt[16 * 32];
__device__ unsigned g_gen[16 * 32];

// group-scoped software barrier (all CTAs of the grid are co-resident; groups
// only couple CTAs that actually exchange h)
__device__ __forceinline__ void group_barrier(int gid, unsigned n) {
    __syncthreads();
    if (threadIdx.x == 0) {
        volatile unsigned* genp = &g_gen[gid * 32];
        unsigned gen = *genp;
        __threadfence();
        if (atomicAdd(&g_cnt[gid * 32], 1u) == n - 1u) {
            atomicExch(&g_cnt[gid * 32], 0u);
            __threadfence();
            atomicExch(&g_gen[gid * 32], gen + 1u);
        } else {
            while (*genp == gen) { }
        }
        __threadfence();
    }
    __syncthreads();
}

__global__ void pack_whh(const float* __restrict__ in, float* __restrict__ out, int H) {
    int idx = blockIdx.x * blockDim.x + threadIdx.x;
    if (idx < 4 * H * H) {
        int g = idx & 3;
        int rem = idx >> 2;
        int n = rem % H;
        int k = rem / H;
        out[idx] = in[(size_t)(g * H + n) * H + k];
    }
}

// ---------------- TF32 tensor-core GEMM (round-3, unchanged) -------------------
#define BKK 16
#define SST 136
__global__ void __launch_bounds__(256) gemm_tf32(
    const float* __restrict__ A, const float* __restrict__ W,
    const float* __restrict__ bias, float* __restrict__ C,
    int M, int N, int K)
{
    __shared__ unsigned As[BKK][SST];
    __shared__ unsigned Bs[BKK][SST];
    int tid = threadIdx.x;
    int lane = tid & 31, wid = tid >> 5;
    int wm = wid >> 2, wn = wid & 3;
    int lq = lane >> 2, lr4 = lane & 3;
    const float* Ab = A + (size_t)blockIdx.y * 128 * K;
    const float* Wb = W + (size_t)blockIdx.x * 128 * K;
    int ldr = tid >> 1;
    int ldk = (tid & 1) * 8;

    float acc[4][4][4];
#pragma unroll
    for (int i = 0; i < 4; i++)
#pragma unroll
        for (int j = 0; j < 4; j++)
#pragma unroll
            for (int r = 0; r < 4; r++) acc[i][j][r] = 0.f;

    for (int k0 = 0; k0 < K; k0 += BKK) {
        float4 a0 = *(const float4*)(Ab + (size_t)ldr * K + k0 + ldk);
        float4 a1 = *(const float4*)(Ab + (size_t)ldr * K + k0 + ldk + 4);
        float4 w0 = *(const float4*)(Wb + (size_t)ldr * K + k0 + ldk);
        float4 w1 = *(const float4*)(Wb + (size_t)ldr * K + k0 + ldk + 4);
        As[ldk + 0][ldr] = cvt_tf32(a0.x); As[ldk + 1][ldr] = cvt_tf32(a0.y);
        As[ldk + 2][ldr] = cvt_tf32(a0.z); As[ldk + 3][ldr] = cvt_tf32(a0.w);
        As[ldk + 4][ldr] = cvt_tf32(a1.x); As[ldk + 5][ldr] = cvt_tf32(a1.y);
        As[ldk + 6][ldr] = cvt_tf32(a1.z); As[ldk + 7][ldr] = cvt_tf32(a1.w);
        Bs[ldk + 0][ldr] = cvt_tf32(w0.x); Bs[ldk + 1][ldr] = cvt_tf32(w0.y);
        Bs[ldk + 2][ldr] = cvt_tf32(w0.z); Bs[ldk + 3][ldr] = cvt_tf32(w0.w);
        Bs[ldk + 4][ldr] = cvt_tf32(w1.x); Bs[ldk + 5][ldr] = cvt_tf32(w1.y);
        Bs[ldk + 6][ldr] = cvt_tf32(w1.z); Bs[ldk + 7][ldr] = cvt_tf32(w1.w);
        __syncthreads();
#pragma unroll
        for (int ks = 0; ks < 2; ks++) {
            int kb = ks * 8;
            unsigned af[4][4];
#pragma unroll
            for (int mf = 0; mf < 4; mf++) {
                int row = wm * 64 + mf * 16 + lq;
                af[mf][0] = As[kb + lr4][row];
                af[mf][1] = As[kb + lr4][row + 8];
                af[mf][2] = As[kb + lr4 + 4][row];
                af[mf][3] = As[kb + lr4 + 4][row + 8];
            }
            unsigned bf[4][2];
#pragma unroll
            for (int nf = 0; nf < 4; nf++) {
                int n = wn * 32 + nf * 8 + lq;
                bf[nf][0] = Bs[kb + lr4][n];
                bf[nf][1] = Bs[kb + lr4 + 4][n];
            }
#pragma unroll
            for (int mf = 0; mf < 4; mf++)
#pragma unroll
                for (int nf = 0; nf < 4; nf++)
                    mma_tf32(acc[mf][nf], af[mf], bf[nf]);
        }
        __syncthreads();
    }
#pragma unroll
    for (int nf = 0; nf < 4; nf++) {
        int col0 = blockIdx.x * 128 + wn * 32 + nf * 8 + 2 * lr4;
        float b0v = bias[col0], b1v = bias[col0 + 1];
#pragma unroll
        for (int mf = 0; mf < 4; mf++) {
            int row0 = blockIdx.y * 128 + wm * 64 + mf * 16 + lq;
            float2 o0 = make_float2(acc[mf][nf][0] + b0v, acc[mf][nf][1] + b1v);
            float2 o1 = make_float2(acc[mf][nf][2] + b0v, acc[mf][nf][3] + b1v);
            *(float2*)(C + (size_t)row0 * N + col0) = o0;
            *(float2*)(C + (size_t)(row0 + 8) * N + col0) = o1;
        }
    }
}

__device__ __forceinline__ float sigf(float x) { return 1.f / (1.f + __expf(-x)); }

// ---------------- word BiLSTM scan: weights resident in smem -------------------
// 128 CTAs: dir(2) x bt(8) x nt(8). CTA = 32b x 32n. Group = 8 CTAs sharing (dir,bt).
__global__ void __launch_bounds__(256) word_scan_kernel() {
    extern __shared__ __align__(16) float Ws[];      // [256][128] = 128KB
    int cta = blockIdx.x;
    int dir = cta & 1;
    int id = cta >> 1;
    int bt = id >> 3, nt = id & 7;
    int gid = dir * 8 + bt;
    const float* gxp = dir ? (g_big + GXR_OFF) : g_big;
    const float* wp  = dir ? g_wpr : g_wpf;
    int tid = threadIdx.x;
    int lane = tid & 31, wg = tid >> 5;
    int n = nt * 32 + lane;
    int b0 = bt * 32 + wg * 4;

    // weight slice -> smem once (cols nt*128 .. +127 of packed [k][n*4+g])
    for (int i = tid; i < 256 * 32; i += 256) {
        int k = i >> 5, j4 = i & 31;
        ((float4*)Ws)[i] = *(const float4*)(wp + (size_t)k * G4 + nt * 128 + j4 * 4);
    }
    float* hb0 = &g_hw[dir][0][0][0];
    float* hb1 = &g_hw[dir][1][0][0];
    float c_reg[4] = {0.f, 0.f, 0.f, 0.f};
#pragma unroll
    for (int u = 0; u < 4; u++) hb0[(size_t)(b0 + u) * HH + n] = 0.f;
    group_barrier(gid, 8);

    for (int t = 0; t < Tt; t++) {
        int tt = dir ? (Tt - 1 - t) : t;
        const float* hp = (t & 1) ? hb1 : hb0;
        float* hn = (t & 1) ? hb0 : hb1;
        ull a01[4], a23[4];
#pragma unroll
        for (int u = 0; u < 4; u++) {
            const float* gp = gxp + ((size_t)(b0 + u) * Tt + tt) * G4 + n;
            a01[u] = pk2(gp[0], gp[HH]);
            a23[u] = pk2(gp[2 * HH], gp[3 * HH]);
        }
        const float* h0p = hp + (size_t)b0 * HH;
        const float* wrow = Ws + lane * 4;
#pragma unroll 8
        for (int k = 0; k < HH; k++) {
            ulonglong2 wv = *(const ulonglong2*)(wrow + k * 128);
            float v0 = h0p[k], v1 = h0p[HH + k], v2 = h0p[2 * HH + k], v3 = h0p[3 * HH + k];
            ull h0 = pk2(v0, v0), h1 = pk2(v1, v1), h2 = pk2(v2, v2), h3 = pk2(v3, v3);
            fma2(a01[0], h0, wv.x); fma2(a23[0], h0, wv.y);
            fma2(a01[1], h1, wv.x); fma2(a23[1], h1, wv.y);
            fma2(a01[2], h2, wv.x); fma2(a23[2], h2, wv.y);
            fma2(a01[3], h3, wv.x); fma2(a23[3], h3, wv.y);
        }
#pragma unroll
        for (int u = 0; u < 4; u++) {
            float2 p01 = up2(a01[u]);
            float2 p23 = up2(a23[u]);
            float ig = sigf(p01.x), fg = sigf(p01.y);
            float gg = tanhf(p23.x), og = sigf(p23.y);
            c_reg[u] = fg * c_reg[u] + ig * gg;
            float h = og * tanhf(c_reg[u]);
            hn[(size_t)(b0 + u) * HH + n] = h;
            g_hcat[((size_t)(b0 + u) * Tt + tt) * H2 + dir * HH + n] = h;
        }
        if (t < Tt - 1) group_barrier(gid, 8);
    }
}

// ---------------- sentence LSTM scan: weights resident in smem -----------------
// 128 CTAs: bt(4) x nt(32). CTA = 64b x 16n. Group = 32 CTAs sharing bt.
__global__ void __launch_bounds__(256) sent_scan_kernel() {
    extern __shared__ __align__(16) float Ws[];      // [512][64] = 128KB
    int cta = blockIdx.x;
    int bt = cta >> 5, nt = cta & 31;
    int tid = threadIdx.x;
    int lane = tid & 31, wg = tid >> 5;
    int nl = lane & 15, half = lane >> 4;
    int n = nt * 16 + nl;
    int b0 = bt * 64 + wg * 8 + half * 4;

    for (int i = tid; i < 512 * 16; i += 256) {
        int k = i >> 4, j4 = i & 15;
        ((float4*)Ws)[i] = *(const float4*)(g_wps + (size_t)k * G8 + nt * 64 + j4 * 4);
    }
    float* hb0 = &g_hs[0][0][0];
    float* hb1 = &g_hs[1][0][0];
    float c_reg[4] = {0.f, 0.f, 0.f, 0.f};
#pragma unroll
    for (int u = 0; u < 4; u++) hb0[(size_t)(b0 + u) * H2 + n] = 0.f;
    group_barrier(bt, 32);

    for (int t = 0; t < Tt; t++) {
        const float* hp = (t & 1) ? hb1 : hb0;
        float* hn = (t & 1) ? hb0 : hb1;
        ull a01[4], a23[4];
#pragma unroll
        for (int u = 0; u < 4; u++) {
            const float* gp = g_big + ((size_t)(b0 + u) * Tt + t) * G8 + n;
            a01[u] = pk2(gp[0], gp[H2]);
            a23[u] = pk2(gp[2 * H2], gp[3 * H2]);
        }
        const float* h0p = hp + (size_t)b0 * H2;
        const float* wrow = Ws + nl * 4;
#pragma unroll 8
        for (int k = 0; k < H2; k++) {
            ulonglong2 wv = *(const ulonglong2*)(wrow + k * 64);
            float v0 = h0p[k], v1 = h0p[H2 + k], v2 = h0p[2 * H2 + k], v3 = h0p[3 * H2 + k];
            ull h0 = pk2(v0, v0), h1 = pk2(v1, v1), h2 = pk2(v2, v2), h3 = pk2(v3, v3);
            fma2(a01[0], h0, wv.x); fma2(a23[0], h0, wv.y);
            fma2(a01[1], h1, wv.x); fma2(a23[1], h1, wv.y);
            fma2(a01[2], h2, wv.x); fma2(a23[2], h2, wv.y);
            fma2(a01[3], h3, wv.x); fma2(a23[3], h3, wv.y);
        }
#pragma unroll
        for (int u = 0; u < 4; u++) {
            float2 p01 = up2(a01[u]);
            float2 p23 = up2(a23[u]);
            float ig = sigf(p01.x), fg = sigf(p01.y);
            float gg = tanhf(p23.x), og = sigf(p23.y);
            c_reg[u] = fg * c_reg[u] + ig * gg;
            float h = og * tanhf(c_reg[u]);
            hn[(size_t)(b0 + u) * H2 + n] = h;   // t=127 -> hb0 = hT
        }
        if (t < Tt - 1) group_barrier(bt, 32);
    }
}

// ---------------- emissions + CRF (single block) ------------------------------
__global__ void __launch_bounds__(256) crf_kernel(
    const int* __restrict__ y,
    const float* __restrict__ lin_w, const float* __restrict__ lin_b,
    const float* __restrict__ cstart, const float* __restrict__ cend,
    const float* __restrict__ ctrans, float* __restrict__ out)
{
    __shared__ float pool[NC * H2];
    __shared__ float e[Bq][NC];
    int tid = threadIdx.x;

    for (int idx = tid; idx < NC * H2 / 4; idx += 256)
        ((float4*)pool)[idx] = ((const float4*)lin_w)[idx];
    __syncthreads();
    {
        const float* hrow = &g_hs[0][tid][0];
        float acc[NC];
#pragma unroll
        for (int c = 0; c < NC; c++) acc[c] = lin_b[c];
        for (int k = 0; k < H2; k += 4) {
            float4 hv = *(const float4*)(hrow + k);
#pragma unroll
            for (int c = 0; c < NC; c++) {
                const float* wr = pool + c * H2 + k;
                acc[c] += hv.x * wr[0] + hv.y * wr[1] + hv.z * wr[2] + hv.w * wr[3];
            }
        }
#pragma unroll
        for (int c = 0; c < NC; c++) e[tid][c] = acc[c];
    }
    __syncthreads();
    if (tid < NC * NC) pool[tid] = ctrans[tid];
    __syncthreads();
    float* tr = pool;
    float* alpha = pool + 256;
    float* alpha2 = pool + 288;
    if (tid < NC) alpha[tid] = cstart[tid] + e[0][tid];
    __syncthreads();
    if (tid < 32) {
        for (int s = 1; s < Bq; s++) {
            if (tid < NC) {
                int j = tid;
                float m = -1e30f;
#pragma unroll
                for (int i = 0; i < NC; i++) m = fmaxf(m, alpha[i] + tr[i * NC + j]);
                float sum = 0.f;
#pragma unroll
                for (int i = 0; i < NC; i++) sum += expf(alpha[i] + tr[i * NC + j] - m);
                alpha2[j] = m + logf(sum) + e[s][j];
            }
            __syncwarp();
            if (tid < NC) alpha[tid] = alpha2[tid];
            __syncwarp();
        }
    }
    __syncthreads();
    if (tid == 0) {
        int yprev = y[0];
        float num = cstart[yprev] + e[0][yprev];
        for (int s = 1; s < Bq; s++) {
            int ys = y[s];
            num += tr[yprev * NC + ys] + e[s][ys];
            yprev = ys;
        }
        num += cend[yprev];
        float m = -1e30f;
        for (int i = 0; i < NC; i++) m = fmaxf(m, alpha[i] + cend[i]);
        float sum = 0.f;
        for (int i = 0; i < NC; i++) sum += expf(alpha[i] + cend[i] - m);
        out[0] = num - (m + logf(sum));
    }
}

// ---------------- launch ------------------------------------------------------
extern "C" void kernel_launch(void* const* d_in, const int* in_sizes, int n_in,
                              void* d_out, int out_size)
{
    const float* x      = (const float*)d_in[0];
    const int*   y      = (const int*)  d_in[1];
    const float* w_ih_f = (const float*)d_in[3];
    const float* w_hh_f = (const float*)d_in[4];
    const float* b_f    = (const float*)d_in[5];
    const float* w_ih_r = (const float*)d_in[6];
    const float* w_hh_r = (const float*)d_in[7];
    const float* b_r    = (const float*)d_in[8];
    const float* w_ih_s = (const float*)d_in[9];
    const float* w_hh_s = (const float*)d_in[10];
    const float* b_s    = (const float*)d_in[11];
    const float* lin_w  = (const float*)d_in[12];
    const float* lin_b  = (const float*)d_in[13];
    const float* cstart = (const float*)d_in[14];
    const float* cend   = (const float*)d_in[15];
    const float* ctrans = (const float*)d_in[16];
    float* out = (float*)d_out;

    float *gbig, *hcat, *wpf, *wpr, *wps;
    cudaGetSymbolAddress((void**)&gbig, g_big);
    cudaGetSymbolAddress((void**)&hcat, g_hcat);
    cudaGetSymbolAddress((void**)&wpf, g_wpf);
    cudaGetSymbolAddress((void**)&wpr, g_wpr);
    cudaGetSymbolAddress((void**)&wps, g_wps);

    cudaFuncSetAttribute(word_scan_kernel,
                         cudaFuncAttributeMaxDynamicSharedMemorySize, 131072);
    cudaFuncSetAttribute(sent_scan_kernel,
                         cudaFuncAttributeMaxDynamicSharedMemorySize, 131072);

    pack_whh<<<(4 * HH * HH + 255) / 256, 256>>>(w_hh_f, wpf, HH);
    pack_whh<<<(4 * HH * HH + 255) / 256, 256>>>(w_hh_r, wpr, HH);
    pack_whh<<<(4 * H2 * H2 + 255) / 256, 256>>>(w_hh_s, wps, H2);

    dim3 g1(G4 / 128, (Bq * Tt) / 128);
    gemm_tf32<<<g1, 256>>>(x, w_ih_f, b_f, gbig, Bq * Tt, G4, Ff);
    gemm_tf32<<<g1, 256>>>(x, w_ih_r, b_r, gbig + GXR_OFF, Bq * Tt, G4, Ff);

    word_scan_kernel<<<128, 256, 131072>>>();

    dim3 g2(G8 / 128, (Bq * Tt) / 128);
    gemm_tf32<<<g2, 256>>>(hcat, w_ih_s, b_s, gbig, Bq * Tt, G8, H2);

    sent_scan_kernel<<<128, 256, 131072>>>();

    crf_kernel<<<1, 256>>>(y, lin_w, lin_b, cstart, cend, ctrans, out);
}